// round 5
// baseline (speedup 1.0000x reference)
#include <cuda_runtime.h>

#define N_NODES 100000
#define N_EDGES 1600000
#define F_IN    128
#define F_HID   64
#define F_OUT   47
#define F_OUT_P 48   // padded

// ---------------- scratch (allocation-guard compliant) ----------------
// Layer outputs pre-scaled by dinv[row]:  y = (xW) * rsqrt(deg)
__device__ __align__(16) float g_y1  [N_NODES * F_HID];
__device__ __align__(16) float g_agg1[N_NODES * F_HID];
__device__ __align__(16) float g_y2  [N_NODES * F_OUT_P];
__device__ __align__(16) float g_agg2[N_NODES * F_OUT_P];
__device__ float g_deg[N_NODES];

// Vectorized reduction (sm_90+): 1 RED op moves 16B
__device__ __forceinline__ void red_add_v4(float* addr, float4 v) {
    asm volatile("red.global.add.v4.f32 [%0], {%1,%2,%3,%4};"
                 :: "l"(addr), "f"(v.x), "f"(v.y), "f"(v.z), "f"(v.w)
                 : "memory");
}

// ---------------- degree ----------------
__global__ void k_deg_init() {
    int i = blockIdx.x * 256 + threadIdx.x;
    if (i < N_NODES) g_deg[i] = 1.0f;          // A + I: start at 1
}

__global__ void k_deg_count(const int* __restrict__ dst) {
    int e = blockIdx.x * 256 + threadIdx.x;
    if (e < N_EDGES) atomicAdd(&g_deg[dst[e]], 1.0f);   // REDG
}

// ---------------- GEMM1: y1[N,64] = (x[N,128] @ W1) * dinv[row] ----------------
// 256 thr: col = t&63, rowgroup rg = t>>6, each thread -> 4 rows x 1 col.
// Epilogue writes y1 to BOTH g_y1 and g_agg1 (self-loop init folded in).
__global__ void k_gemm1(const float* __restrict__ x, const float* __restrict__ W1) {
    __shared__ float  ws[F_IN * F_HID];       // 32 KB
    __shared__ float4 xs[16][F_IN / 4];       // 8 KB
    int t = threadIdx.x;
    for (int i = t; i < F_IN * F_HID; i += 256) ws[i] = W1[i];
    int row0 = blockIdx.x * 16;
    const float4* xg = (const float4*)x + (size_t)row0 * (F_IN / 4);
    for (int i = t; i < 16 * (F_IN / 4); i += 256) xs[i >> 5][i & 31] = xg[i];
    __syncthreads();

    int col = t & 63;
    int rg  = t >> 6;                          // 0..3
    float acc0 = 0.f, acc1 = 0.f, acc2 = 0.f, acc3 = 0.f;
#pragma unroll 8
    for (int k4 = 0; k4 < F_IN / 4; ++k4) {
        float4 a0 = xs[rg * 4 + 0][k4];        // broadcast LDS within warp
        float4 a1 = xs[rg * 4 + 1][k4];
        float4 a2 = xs[rg * 4 + 2][k4];
        float4 a3 = xs[rg * 4 + 3][k4];
        int k = k4 * 4;
        float w0 = ws[(k + 0) * F_HID + col];  // conflict-free LDS
        float w1 = ws[(k + 1) * F_HID + col];
        float w2 = ws[(k + 2) * F_HID + col];
        float w3 = ws[(k + 3) * F_HID + col];
        acc0 += a0.x * w0; acc0 += a0.y * w1; acc0 += a0.z * w2; acc0 += a0.w * w3;
        acc1 += a1.x * w0; acc1 += a1.y * w1; acc1 += a1.z * w2; acc1 += a1.w * w3;
        acc2 += a2.x * w0; acc2 += a2.y * w1; acc2 += a2.z * w2; acc2 += a2.w * w3;
        acc3 += a3.x * w0; acc3 += a3.y * w1; acc3 += a3.z * w2; acc3 += a3.w * w3;
    }
    int r = row0 + rg * 4;
    float d0 = rsqrtf(g_deg[r + 0]);
    float d1 = rsqrtf(g_deg[r + 1]);
    float d2 = rsqrtf(g_deg[r + 2]);
    float d3 = rsqrtf(g_deg[r + 3]);
    acc0 *= d0; acc1 *= d1; acc2 *= d2; acc3 *= d3;
    g_y1  [(size_t)(r + 0) * F_HID + col] = acc0;
    g_y1  [(size_t)(r + 1) * F_HID + col] = acc1;
    g_y1  [(size_t)(r + 2) * F_HID + col] = acc2;
    g_y1  [(size_t)(r + 3) * F_HID + col] = acc3;
    g_agg1[(size_t)(r + 0) * F_HID + col] = acc0;   // self-loop init
    g_agg1[(size_t)(r + 1) * F_HID + col] = acc1;
    g_agg1[(size_t)(r + 2) * F_HID + col] = acc2;
    g_agg1[(size_t)(r + 3) * F_HID + col] = acc3;
}

// ---------------- edge scatter: agg[dst] += y[src]  (pure, no norm) ----------------
// 16 consecutive threads share one edge -> 256B gather fully coalesced.
__global__ void k_scatter1(const int* __restrict__ src, const int* __restrict__ dst) {
    int idx = blockIdx.x * 256 + threadIdx.x;
    if (idx >= N_EDGES * 16) return;
    int e = idx >> 4, c = idx & 15;
    int s = src[e], d = dst[e];
    float4 v = ((const float4*)g_y1)[(size_t)s * 16 + c];
    red_add_v4((float*)((float4*)g_agg1 + ((size_t)d * 16 + c)), v);
}

__global__ void k_scatter2(const int* __restrict__ src, const int* __restrict__ dst) {
    int idx = blockIdx.x * 256 + threadIdx.x;
    if (idx >= N_EDGES * 12) return;
    int e = idx / 12, c = idx - e * 12;
    int s = src[e], d = dst[e];
    float4 v = ((const float4*)g_y2)[(size_t)s * 12 + c];
    red_add_v4((float*)((float4*)g_agg2 + ((size_t)d * 12 + c)), v);
}

// ---------------- GEMM2: y2[N,48] = (relu(dinv*agg1 + b1) @ W2pad) * dinv ----------------
// 192 thr: col = t%48, rg = t/48, each thread -> 4 rows x 1 col.
__global__ void k_gemm2(const float* __restrict__ b1, const float* __restrict__ W2) {
    __shared__ float  ws[F_HID * F_OUT_P];    // 12 KB (col 47 zero-padded)
    __shared__ float4 xs[16][F_HID / 4];      // 4 KB
    int t = threadIdx.x;
    for (int i = t; i < F_HID * F_OUT_P; i += 192) {
        int k = i / F_OUT_P, c = i - k * F_OUT_P;
        ws[i] = (c < F_OUT) ? W2[k * F_OUT + c] : 0.0f;
    }
    int row0 = blockIdx.x * 16;
    const float4* hb  = (const float4*)g_agg1 + (size_t)row0 * (F_HID / 4);
    const float4* b1v = (const float4*)b1;
    for (int i = t; i < 16 * (F_HID / 4); i += 192) {
        int row = row0 + (i >> 4);
        float di = rsqrtf(g_deg[row]);        // deferred dst-side scale
        float4 v = hb[i];
        float4 b = b1v[i & 15];
        float4 h;
        h.x = fmaxf(fmaf(v.x, di, b.x), 0.f);
        h.y = fmaxf(fmaf(v.y, di, b.y), 0.f);
        h.z = fmaxf(fmaf(v.z, di, b.z), 0.f);
        h.w = fmaxf(fmaf(v.w, di, b.w), 0.f);
        xs[i >> 4][i & 15] = h;
    }
    __syncthreads();

    int col = t % F_OUT_P;
    int rg  = t / F_OUT_P;                    // 0..3
    float acc0 = 0.f, acc1 = 0.f, acc2 = 0.f, acc3 = 0.f;
#pragma unroll 8
    for (int k4 = 0; k4 < F_HID / 4; ++k4) {
        float4 a0 = xs[rg * 4 + 0][k4];
        float4 a1 = xs[rg * 4 + 1][k4];
        float4 a2 = xs[rg * 4 + 2][k4];
        float4 a3 = xs[rg * 4 + 3][k4];
        int k = k4 * 4;
        float w0 = ws[(k + 0) * F_OUT_P + col];
        float w1 = ws[(k + 1) * F_OUT_P + col];
        float w2 = ws[(k + 2) * F_OUT_P + col];
        float w3 = ws[(k + 3) * F_OUT_P + col];
        acc0 += a0.x * w0; acc0 += a0.y * w1; acc0 += a0.z * w2; acc0 += a0.w * w3;
        acc1 += a1.x * w0; acc1 += a1.y * w1; acc1 += a1.z * w2; acc1 += a1.w * w3;
        acc2 += a2.x * w0; acc2 += a2.y * w1; acc2 += a2.z * w2; acc2 += a2.w * w3;
        acc3 += a3.x * w0; acc3 += a3.y * w1; acc3 += a3.z * w2; acc3 += a3.w * w3;
    }
    int r = row0 + rg * 4;
    float d0 = rsqrtf(g_deg[r + 0]);
    float d1 = rsqrtf(g_deg[r + 1]);
    float d2 = rsqrtf(g_deg[r + 2]);
    float d3 = rsqrtf(g_deg[r + 3]);
    acc0 *= d0; acc1 *= d1; acc2 *= d2; acc3 *= d3;
    g_y2  [(size_t)(r + 0) * F_OUT_P + col] = acc0;
    g_y2  [(size_t)(r + 1) * F_OUT_P + col] = acc1;
    g_y2  [(size_t)(r + 2) * F_OUT_P + col] = acc2;
    g_y2  [(size_t)(r + 3) * F_OUT_P + col] = acc3;
    g_agg2[(size_t)(r + 0) * F_OUT_P + col] = acc0;  // self-loop init
    g_agg2[(size_t)(r + 1) * F_OUT_P + col] = acc1;
    g_agg2[(size_t)(r + 2) * F_OUT_P + col] = acc2;
    g_agg2[(size_t)(r + 3) * F_OUT_P + col] = acc3;
}

// ---------------- log_softmax(dinv*agg2 + b2) over 47 cols, one warp/row ----------------
__global__ void k_out(const float* __restrict__ b2, float* __restrict__ out) {
    int warp = threadIdx.x >> 5;
    int lane = threadIdx.x & 31;
    int row  = blockIdx.x * 8 + warp;
    if (row >= N_NODES) return;
    float di = rsqrtf(g_deg[row]);            // deferred dst-side scale
    const float* r = g_agg2 + (size_t)row * F_OUT_P;
    int  c1  = lane + 32;
    bool ok1 = (c1 < F_OUT);
    float v0 = fmaf(r[lane], di, b2[lane]);
    float v1 = ok1 ? fmaf(r[c1], di, b2[c1]) : -1e30f;

    float m = fmaxf(v0, v1);
#pragma unroll
    for (int off = 16; off > 0; off >>= 1)
        m = fmaxf(m, __shfl_xor_sync(0xffffffffu, m, off));

    float s = expf(v0 - m) + (ok1 ? expf(v1 - m) : 0.0f);
#pragma unroll
    for (int off = 16; off > 0; off >>= 1)
        s += __shfl_xor_sync(0xffffffffu, s, off);

    float ls = m + logf(s);
    out[(size_t)row * F_OUT + lane] = v0 - ls;
    if (ok1) out[(size_t)row * F_OUT + c1] = v1 - ls;
}

// ---------------- launch (7 graph-capturable kernels) ----------------
extern "C" void kernel_launch(void* const* d_in, const int* in_sizes, int n_in,
                              void* d_out, int out_size) {
    const float* x  = (const float*)d_in[0];
    const int*   ei = (const int*)  d_in[1];
    const float* W1 = (const float*)d_in[2];
    const float* b1 = (const float*)d_in[3];
    const float* W2 = (const float*)d_in[4];
    const float* b2 = (const float*)d_in[5];
    float* out = (float*)d_out;
    const int* src = ei;
    const int* dst = ei + N_EDGES;

    k_deg_init <<<(N_NODES + 255) / 256, 256>>>();
    k_deg_count<<<(N_EDGES + 255) / 256, 256>>>(dst);

    k_gemm1    <<<N_NODES / 16, 256>>>(x, W1);
    k_scatter1 <<<(N_EDGES * 16 + 255) / 256, 256>>>(src, dst);

    k_gemm2    <<<N_NODES / 16, 192>>>(b1, W2);
    k_scatter2 <<<(N_EDGES * 12 + 255) / 256, 256>>>(src, dst);

    k_out      <<<(N_NODES + 7) / 8, 256>>>(b2, out);
}

// round 8
// speedup vs baseline: 1.9605x; 1.9605x over previous
#include <cuda_runtime.h>

#define N_NODES 100000
#define N_EDGES 1600000
#define F_IN    128
#define F_HID   64
#define F_OUT   47
#define F_OUT_P 48   // padded

#define NBLK_N  391          // ceil(100000/256)

// ---------------- scratch (allocation-guard compliant) ----------------
__device__ __align__(16) float g_y1[N_NODES * F_HID];    // (x@W1)*dinv[row]
__device__ __align__(16) float g_h1[N_NODES * F_HID];    // relu(dinv*agg1+b1)
__device__ __align__(16) float g_y2[N_NODES * F_OUT_P];  // (h@W2)*dinv[row]
__device__ float g_dinv[N_NODES];
__device__ int   g_cnt   [N_NODES];
__device__ int   g_cursor[N_NODES];
__device__ int   g_row_ptr[N_NODES + 1];
__device__ int   g_part[512];
__device__ int   g_col[N_EDGES];                         // CSR column (src) list

// ---------------- CSR build ----------------
__global__ void k_zero_cnt() {
    int i = blockIdx.x * 256 + threadIdx.x;
    if (i < N_NODES) g_cnt[i] = 0;
}

__global__ void k_cnt(const int* __restrict__ dst) {
    int e = blockIdx.x * 256 + threadIdx.x;
    if (e < N_EDGES) atomicAdd(&g_cnt[dst[e]], 1);
}

// per-block inclusive scan (Hillis–Steele) -> exclusive; block totals to g_part
__global__ void k_scan_blk() {
    __shared__ int sh[256];
    int i = blockIdx.x * 256 + threadIdx.x;
    int v = (i < N_NODES) ? g_cnt[i] : 0;
    sh[threadIdx.x] = v;
    __syncthreads();
#pragma unroll
    for (int off = 1; off < 256; off <<= 1) {
        int t = (threadIdx.x >= off) ? sh[threadIdx.x - off] : 0;
        __syncthreads();
        sh[threadIdx.x] += t;
        __syncthreads();
    }
    if (i < N_NODES) g_row_ptr[i] = sh[threadIdx.x] - v;   // exclusive, pre-offset
    if (threadIdx.x == 255) g_part[blockIdx.x] = sh[255];
}

// single-block exclusive scan of the 391 block totals
__global__ void k_scan_part() {
    __shared__ int sh[512];
    int t = threadIdx.x;
    int v = (t < NBLK_N) ? g_part[t] : 0;
    sh[t] = v;
    __syncthreads();
#pragma unroll
    for (int off = 1; off < 512; off <<= 1) {
        int u = (t >= off) ? sh[t - off] : 0;
        __syncthreads();
        sh[t] += u;
        __syncthreads();
    }
    if (t < NBLK_N) g_part[t] = sh[t] - v;                 // exclusive
}

// add block offsets; init cursor; dinv = rsqrt(cnt+1); row_ptr[N]=E
__global__ void k_scan_fix() {
    int i = blockIdx.x * 256 + threadIdx.x;
    if (i < N_NODES) {
        int rp = g_row_ptr[i] + g_part[i >> 8];
        g_row_ptr[i] = rp;
        g_cursor[i]  = rp;
        g_dinv[i]    = rsqrtf((float)(g_cnt[i] + 1));      // deg = cnt + 1 (self-loop)
    }
    if (i == 0) g_row_ptr[N_NODES] = N_EDGES;
}

__global__ void k_fill(const int* __restrict__ src, const int* __restrict__ dst) {
    int e = blockIdx.x * 256 + threadIdx.x;
    if (e < N_EDGES) {
        int pos = atomicAdd(&g_cursor[dst[e]], 1);
        g_col[pos] = src[e];
    }
}

// ---------------- GEMM1: y1[N,64] = (x[N,128] @ W1) * dinv[row] ----------------
__global__ void k_gemm1(const float* __restrict__ x, const float* __restrict__ W1) {
    __shared__ float  ws[F_IN * F_HID];       // 32 KB
    __shared__ float4 xs[16][F_IN / 4];       // 8 KB
    int t = threadIdx.x;
    for (int i = t; i < F_IN * F_HID; i += 256) ws[i] = W1[i];
    int row0 = blockIdx.x * 16;
    const float4* xg = (const float4*)x + (size_t)row0 * (F_IN / 4);
    for (int i = t; i < 16 * (F_IN / 4); i += 256) xs[i >> 5][i & 31] = xg[i];
    __syncthreads();

    int col = t & 63;
    int rg  = t >> 6;                          // 0..3
    float acc0 = 0.f, acc1 = 0.f, acc2 = 0.f, acc3 = 0.f;
#pragma unroll 8
    for (int k4 = 0; k4 < F_IN / 4; ++k4) {
        float4 a0 = xs[rg * 4 + 0][k4];        // warp-broadcast LDS
        float4 a1 = xs[rg * 4 + 1][k4];
        float4 a2 = xs[rg * 4 + 2][k4];
        float4 a3 = xs[rg * 4 + 3][k4];
        int k = k4 * 4;
        float w0 = ws[(k + 0) * F_HID + col];  // conflict-free LDS
        float w1 = ws[(k + 1) * F_HID + col];
        float w2 = ws[(k + 2) * F_HID + col];
        float w3 = ws[(k + 3) * F_HID + col];
        acc0 += a0.x * w0; acc0 += a0.y * w1; acc0 += a0.z * w2; acc0 += a0.w * w3;
        acc1 += a1.x * w0; acc1 += a1.y * w1; acc1 += a1.z * w2; acc1 += a1.w * w3;
        acc2 += a2.x * w0; acc2 += a2.y * w1; acc2 += a2.z * w2; acc2 += a2.w * w3;
        acc3 += a3.x * w0; acc3 += a3.y * w1; acc3 += a3.z * w2; acc3 += a3.w * w3;
    }
    int r = row0 + rg * 4;
    g_y1[(size_t)(r + 0) * F_HID + col] = acc0 * g_dinv[r + 0];
    g_y1[(size_t)(r + 1) * F_HID + col] = acc1 * g_dinv[r + 1];
    g_y1[(size_t)(r + 2) * F_HID + col] = acc2 * g_dinv[r + 2];
    g_y1[(size_t)(r + 3) * F_HID + col] = acc3 * g_dinv[r + 3];
}

// ------- gather1: h1 = relu( dinv·(Σ_nbr y1[nbr] + y1[d]) + b1 ) -------
// (dinv·y1[d] = xw/deg is exactly the self-loop term — NO extra dinv on self!)
// 16 threads per node, each owns one float4 chunk; neighbor loop unrolled x2.
__global__ void k_gather1(const float* __restrict__ b1) {
    int t = threadIdx.x;
    int node = blockIdx.x * 16 + (t >> 4);
    int c = t & 15;
    const float4* y = (const float4*)g_y1;
    float di = g_dinv[node];
    float4 acc = __ldg(&y[(size_t)node * 16 + c]);   // self term: y1[d] (unscaled)
    float4 acc2 = make_float4(0.f, 0.f, 0.f, 0.f);
    int j   = g_row_ptr[node];
    int end = g_row_ptr[node + 1];
    for (; j + 2 <= end; j += 2) {
        int s0 = g_col[j], s1 = g_col[j + 1];
        float4 v0 = __ldg(&y[(size_t)s0 * 16 + c]);
        float4 v1 = __ldg(&y[(size_t)s1 * 16 + c]);
        acc.x  += v0.x; acc.y  += v0.y; acc.z  += v0.z; acc.w  += v0.w;
        acc2.x += v1.x; acc2.y += v1.y; acc2.z += v1.z; acc2.w += v1.w;
    }
    if (j < end) {
        int s = g_col[j];
        float4 v = __ldg(&y[(size_t)s * 16 + c]);
        acc.x += v.x; acc.y += v.y; acc.z += v.z; acc.w += v.w;
    }
    acc.x += acc2.x; acc.y += acc2.y; acc.z += acc2.z; acc.w += acc2.w;
    float4 b = ((const float4*)b1)[c];
    float4 h;
    h.x = fmaxf(fmaf(acc.x, di, b.x), 0.f);
    h.y = fmaxf(fmaf(acc.y, di, b.y), 0.f);
    h.z = fmaxf(fmaf(acc.z, di, b.z), 0.f);
    h.w = fmaxf(fmaf(acc.w, di, b.w), 0.f);
    ((float4*)g_h1)[(size_t)node * 16 + c] = h;
}

// ---------------- GEMM2: y2[N,48] = (h1 @ W2pad) * dinv[row] ----------------
__global__ void k_gemm2(const float* __restrict__ W2) {
    __shared__ float  ws[F_HID * F_OUT_P];    // 12 KB (col 47 zero-padded)
    __shared__ float4 xs[16][F_HID / 4];      // 4 KB
    int t = threadIdx.x;
    for (int i = t; i < F_HID * F_OUT_P; i += 192) {
        int k = i / F_OUT_P, c = i - k * F_OUT_P;
        ws[i] = (c < F_OUT) ? W2[k * F_OUT + c] : 0.0f;
    }
    int row0 = blockIdx.x * 16;
    const float4* hb = (const float4*)g_h1 + (size_t)row0 * (F_HID / 4);
    for (int i = t; i < 16 * (F_HID / 4); i += 192) xs[i >> 4][i & 15] = hb[i];
    __syncthreads();

    int col = t % F_OUT_P;
    int rg  = t / F_OUT_P;                    // 0..3
    float acc0 = 0.f, acc1 = 0.f, acc2 = 0.f, acc3 = 0.f;
#pragma unroll 8
    for (int k4 = 0; k4 < F_HID / 4; ++k4) {
        float4 a0 = xs[rg * 4 + 0][k4];
        float4 a1 = xs[rg * 4 + 1][k4];
        float4 a2 = xs[rg * 4 + 2][k4];
        float4 a3 = xs[rg * 4 + 3][k4];
        int k = k4 * 4;
        float w0 = ws[(k + 0) * F_OUT_P + col];
        float w1 = ws[(k + 1) * F_OUT_P + col];
        float w2 = ws[(k + 2) * F_OUT_P + col];
        float w3 = ws[(k + 3) * F_OUT_P + col];
        acc0 += a0.x * w0; acc0 += a0.y * w1; acc0 += a0.z * w2; acc0 += a0.w * w3;
        acc1 += a1.x * w0; acc1 += a1.y * w1; acc1 += a1.z * w2; acc1 += a1.w * w3;
        acc2 += a2.x * w0; acc2 += a2.y * w1; acc2 += a2.z * w2; acc2 += a2.w * w3;
        acc3 += a3.x * w0; acc3 += a3.y * w1; acc3 += a3.z * w2; acc3 += a3.w * w3;
    }
    int r = row0 + rg * 4;
    g_y2[(size_t)(r + 0) * F_OUT_P + col] = acc0 * g_dinv[r + 0];
    g_y2[(size_t)(r + 1) * F_OUT_P + col] = acc1 * g_dinv[r + 1];
    g_y2[(size_t)(r + 2) * F_OUT_P + col] = acc2 * g_dinv[r + 2];
    g_y2[(size_t)(r + 3) * F_OUT_P + col] = acc3 * g_dinv[r + 3];
}

// ------- gather2 + fused log-softmax: out = logsoftmax( dinv·(Σ + y2[d]) + b2 ) -------
// 16 threads per node; lanes 0..11 own one float4 chunk (48 padded cols),
// lanes 12..15 idle through the loop and pad the 16-lane reductions.
__global__ void k_gather2(const float* __restrict__ b2, float* __restrict__ out) {
    int t = threadIdx.x;
    int node = blockIdx.x * 16 + (t >> 4);
    int c = t & 15;
    bool act = (c < 12);
    float di = g_dinv[node];
    float4 v = make_float4(-1e30f, -1e30f, -1e30f, -1e30f);

    if (act) {
        const float4* y = (const float4*)g_y2;
        float4 acc = __ldg(&y[(size_t)node * 12 + c]);   // self term (unscaled)
        float4 acc2 = make_float4(0.f, 0.f, 0.f, 0.f);
        int j   = g_row_ptr[node];
        int end = g_row_ptr[node + 1];
        for (; j + 2 <= end; j += 2) {
            int s0 = g_col[j], s1 = g_col[j + 1];
            float4 v0 = __ldg(&y[(size_t)s0 * 12 + c]);
            float4 v1 = __ldg(&y[(size_t)s1 * 12 + c]);
            acc.x  += v0.x; acc.y  += v0.y; acc.z  += v0.z; acc.w  += v0.w;
            acc2.x += v1.x; acc2.y += v1.y; acc2.z += v1.z; acc2.w += v1.w;
        }
        if (j < end) {
            int s = g_col[j];
            float4 w = __ldg(&y[(size_t)s * 12 + c]);
            acc.x += w.x; acc.y += w.y; acc.z += w.z; acc.w += w.w;
        }
        acc.x += acc2.x; acc.y += acc2.y; acc.z += acc2.z; acc.w += acc2.w;

        // bias (b2 has exactly 47 floats: scalar loads for the last chunk)
        float bx, by, bz, bw;
        if (c < 11) {
            bx = b2[c * 4 + 0]; by = b2[c * 4 + 1];
            bz = b2[c * 4 + 2]; bw = b2[c * 4 + 3];
        } else {
            bx = b2[44]; by = b2[45]; bz = b2[46]; bw = 0.f;
        }
        v.x = fmaf(acc.x, di, bx);
        v.y = fmaf(acc.y, di, by);
        v.z = fmaf(acc.z, di, bz);
        v.w = (c < 11) ? fmaf(acc.w, di, bw) : -1e30f;   // col 47 is padding
    }

    // 16-lane group reductions (width=16 segments of the warp)
    float m = fmaxf(fmaxf(v.x, v.y), fmaxf(v.z, v.w));
#pragma unroll
    for (int off = 1; off < 16; off <<= 1)
        m = fmaxf(m, __shfl_xor_sync(0xffffffffu, m, off, 16));

    float s = act ? (expf(v.x - m) + expf(v.y - m) + expf(v.z - m) + expf(v.w - m))
                  : 0.f;
#pragma unroll
    for (int off = 1; off < 16; off <<= 1)
        s += __shfl_xor_sync(0xffffffffu, s, off, 16);

    float ls = m + logf(s);
    if (act) {
        size_t base = (size_t)node * F_OUT + c * 4;
        out[base + 0] = v.x - ls;
        out[base + 1] = v.y - ls;
        out[base + 2] = v.z - ls;
        if (c < 11) out[base + 3] = v.w - ls;
    }
}

// ---------------- launch (10 graph-capturable kernels) ----------------
extern "C" void kernel_launch(void* const* d_in, const int* in_sizes, int n_in,
                              void* d_out, int out_size) {
    const float* x  = (const float*)d_in[0];
    const int*   ei = (const int*)  d_in[1];
    const float* W1 = (const float*)d_in[2];
    const float* b1 = (const float*)d_in[3];
    const float* W2 = (const float*)d_in[4];
    const float* b2 = (const float*)d_in[5];
    float* out = (float*)d_out;
    const int* src = ei;
    const int* dst = ei + N_EDGES;

    // CSR build
    k_zero_cnt <<<NBLK_N, 256>>>();
    k_cnt      <<<(N_EDGES + 255) / 256, 256>>>(dst);
    k_scan_blk <<<NBLK_N, 256>>>();
    k_scan_part<<<1, 512>>>();
    k_scan_fix <<<NBLK_N, 256>>>();
    k_fill     <<<(N_EDGES + 255) / 256, 256>>>(src, dst);

    // layer 1
    k_gemm1    <<<N_NODES / 16, 256>>>(x, W1);
    k_gather1  <<<N_NODES / 16, 256>>>(b1);

    // layer 2 + output
    k_gemm2    <<<N_NODES / 16, 192>>>(W2);
    k_gather2  <<<N_NODES / 16, 256>>>(b2, out);
}

// round 10
// speedup vs baseline: 1.9938x; 1.0170x over previous
#include <cuda_runtime.h>

#define N_NODES 100000
#define N_EDGES 1600000
#define F_IN    128
#define F_HID   64
#define F_OUT   47
#define F_OUT_P 48   // padded

#define NBLK_N  391          // ceil(100000/256)

// ---------------- scratch (allocation-guard compliant) ----------------
__device__ __align__(16) float g_y1[N_NODES * F_HID];    // (x@W1)*dinv[row]
__device__ __align__(16) float g_y2[N_NODES * F_OUT_P];  // (h@W2)*dinv[row]
__device__ float g_dinv  [N_NODES];
__device__ int   g_cnt   [N_NODES];
__device__ int   g_start [N_NODES];
__device__ int   g_cursor[N_NODES];
__device__ int   g_alloc;                                // edge-chunk bump allocator
__device__ int   g_col[N_EDGES];                         // CSR column (src) list

// ---------------- CSR build ----------------
__global__ void k_cnt(const int* __restrict__ dst) {
    int e = blockIdx.x * 256 + threadIdx.x;
    if (e < N_EDGES) atomicAdd(&g_cnt[dst[e]], 1);
}

// fused scan: block-local exclusive scan + atomic chunk grab.
// Rows get disjoint [start, start+cnt) ranges covering [0, E); global order of
// chunks is arbitrary (sum is commutative), so no cross-block scan is needed.
__global__ void k_scanfix() {
    __shared__ int sh[256];
    __shared__ int base_sh;
    int t = threadIdx.x;
    int i = blockIdx.x * 256 + t;
    int v = (i < N_NODES) ? g_cnt[i] : 0;
    sh[t] = v;
    __syncthreads();
#pragma unroll
    for (int off = 1; off < 256; off <<= 1) {
        int u = (t >= off) ? sh[t - off] : 0;
        __syncthreads();
        sh[t] += u;
        __syncthreads();
    }
    if (t == 255) base_sh = atomicAdd(&g_alloc, sh[255]);
    __syncthreads();
    if (i < N_NODES) {
        int start = base_sh + sh[t] - v;     // exclusive within block + chunk base
        g_start[i]  = start;
        g_cursor[i] = start;
        g_dinv[i]   = rsqrtf((float)(v + 1));    // deg = cnt + 1 (self-loop)
    }
}

__global__ void k_fill(const int* __restrict__ src, const int* __restrict__ dst) {
    int e = blockIdx.x * 256 + threadIdx.x;
    if (e < N_EDGES) {
        int pos = atomicAdd(&g_cursor[dst[e]], 1);
        g_col[pos] = src[e];
    }
}

// ---------------- GEMM1: y1[N,64] = (x[N,128] @ W1) * dinv[row] ----------------
__global__ void k_gemm1(const float* __restrict__ x, const float* __restrict__ W1) {
    __shared__ float  ws[F_IN * F_HID];       // 32 KB
    __shared__ float4 xs[16][F_IN / 4];       // 8 KB
    int t = threadIdx.x;
    for (int i = t; i < F_IN * F_HID; i += 256) ws[i] = W1[i];
    int row0 = blockIdx.x * 16;
    const float4* xg = (const float4*)x + (size_t)row0 * (F_IN / 4);
    for (int i = t; i < 16 * (F_IN / 4); i += 256) xs[i >> 5][i & 31] = xg[i];
    __syncthreads();

    int col = t & 63;
    int rg  = t >> 6;                          // 0..3
    float acc0 = 0.f, acc1 = 0.f, acc2 = 0.f, acc3 = 0.f;
#pragma unroll 8
    for (int k4 = 0; k4 < F_IN / 4; ++k4) {
        float4 a0 = xs[rg * 4 + 0][k4];        // warp-broadcast LDS
        float4 a1 = xs[rg * 4 + 1][k4];
        float4 a2 = xs[rg * 4 + 2][k4];
        float4 a3 = xs[rg * 4 + 3][k4];
        int k = k4 * 4;
        float w0 = ws[(k + 0) * F_HID + col];  // conflict-free LDS
        float w1 = ws[(k + 1) * F_HID + col];
        float w2 = ws[(k + 2) * F_HID + col];
        float w3 = ws[(k + 3) * F_HID + col];
        acc0 += a0.x * w0; acc0 += a0.y * w1; acc0 += a0.z * w2; acc0 += a0.w * w3;
        acc1 += a1.x * w0; acc1 += a1.y * w1; acc1 += a1.z * w2; acc1 += a1.w * w3;
        acc2 += a2.x * w0; acc2 += a2.y * w1; acc2 += a2.z * w2; acc2 += a2.w * w3;
        acc3 += a3.x * w0; acc3 += a3.y * w1; acc3 += a3.z * w2; acc3 += a3.w * w3;
    }
    int r = row0 + rg * 4;
    g_y1[(size_t)(r + 0) * F_HID + col] = acc0 * g_dinv[r + 0];
    g_y1[(size_t)(r + 1) * F_HID + col] = acc1 * g_dinv[r + 1];
    g_y1[(size_t)(r + 2) * F_HID + col] = acc2 * g_dinv[r + 2];
    g_y1[(size_t)(r + 3) * F_HID + col] = acc3 * g_dinv[r + 3];
}

// ------- fused gather1 + GEMM2 -------
// Phase A (256 thr, 16 thr/node): h = relu( dinv·(Σ_nbr y1[nbr] + y1[d]) + b1 ) -> smem
// Phase B (192 thr): y2[16 rows, 48 cols] = (h @ W2pad) * dinv[row], written direct.
__global__ void k_g1g2(const float* __restrict__ b1, const float* __restrict__ W2) {
    __shared__ float hs[16][F_HID];           // 4 KB
    __shared__ float ws[F_HID][F_OUT_P];      // 12 KB (col 47 zero-padded)
    int t = threadIdx.x;
    for (int i = t; i < F_HID * F_OUT_P; i += 256) {
        int k = i / F_OUT_P, c = i - k * F_OUT_P;
        ws[k][c] = (c < F_OUT) ? W2[k * F_OUT + c] : 0.0f;
    }

    // ---- Phase A: gather ----
    int node = blockIdx.x * 16 + (t >> 4);
    int c = t & 15;
    const float4* y = (const float4*)g_y1;
    float di = g_dinv[node];
    float4 a0 = __ldg(&y[(size_t)node * 16 + c]);   // self term (unscaled!)
    float4 a1 = make_float4(0.f, 0.f, 0.f, 0.f);
    float4 a2 = make_float4(0.f, 0.f, 0.f, 0.f);
    float4 a3 = make_float4(0.f, 0.f, 0.f, 0.f);
    int j   = g_start[node];
    int end = j + g_cnt[node];
    for (; j + 4 <= end; j += 4) {                   // MLP=4
        int s0 = g_col[j + 0], s1 = g_col[j + 1];
        int s2 = g_col[j + 2], s3 = g_col[j + 3];
        float4 v0 = __ldg(&y[(size_t)s0 * 16 + c]);
        float4 v1 = __ldg(&y[(size_t)s1 * 16 + c]);
        float4 v2 = __ldg(&y[(size_t)s2 * 16 + c]);
        float4 v3 = __ldg(&y[(size_t)s3 * 16 + c]);
        a0.x += v0.x; a0.y += v0.y; a0.z += v0.z; a0.w += v0.w;
        a1.x += v1.x; a1.y += v1.y; a1.z += v1.z; a1.w += v1.w;
        a2.x += v2.x; a2.y += v2.y; a2.z += v2.z; a2.w += v2.w;
        a3.x += v3.x; a3.y += v3.y; a3.z += v3.z; a3.w += v3.w;
    }
    for (; j < end; ++j) {
        int s = g_col[j];
        float4 v = __ldg(&y[(size_t)s * 16 + c]);
        a0.x += v.x; a0.y += v.y; a0.z += v.z; a0.w += v.w;
    }
    a0.x += a1.x + a2.x + a3.x;
    a0.y += a1.y + a2.y + a3.y;
    a0.z += a1.z + a2.z + a3.z;
    a0.w += a1.w + a2.w + a3.w;
    float4 b = ((const float4*)b1)[c];
    float4 h;
    h.x = fmaxf(fmaf(a0.x, di, b.x), 0.f);
    h.y = fmaxf(fmaf(a0.y, di, b.y), 0.f);
    h.z = fmaxf(fmaf(a0.z, di, b.z), 0.f);
    h.w = fmaxf(fmaf(a0.w, di, b.w), 0.f);
    *(float4*)&hs[t >> 4][c * 4] = h;
    __syncthreads();

    // ---- Phase B: 16x48 = h[16x64] @ ws[64x48] ----
    // 192 threads: colpair cp = t%24 (cols 2cp, 2cp+1), rowgroup rg = t/24 (2 rows).
    if (t < 192) {
        int cp = t % 24;
        int rg = t / 24;                       // 0..7
        int c0 = cp * 2;
        float acc00 = 0.f, acc01 = 0.f, acc10 = 0.f, acc11 = 0.f;
#pragma unroll 8
        for (int k = 0; k < F_HID; ++k) {
            float va = hs[rg * 2 + 0][k];
            float vb = hs[rg * 2 + 1][k];
            float w0 = ws[k][c0];
            float w1 = ws[k][c0 + 1];
            acc00 += va * w0; acc01 += va * w1;
            acc10 += vb * w0; acc11 += vb * w1;
        }
        int r0 = blockIdx.x * 16 + rg * 2;
        float d0 = g_dinv[r0 + 0];
        float d1 = g_dinv[r0 + 1];
        g_y2[(size_t)(r0 + 0) * F_OUT_P + c0 + 0] = acc00 * d0;
        g_y2[(size_t)(r0 + 0) * F_OUT_P + c0 + 1] = acc01 * d0;
        g_y2[(size_t)(r0 + 1) * F_OUT_P + c0 + 0] = acc10 * d1;
        g_y2[(size_t)(r0 + 1) * F_OUT_P + c0 + 1] = acc11 * d1;
    }
}

// ------- gather2 + fused log-softmax: out = logsoftmax( dinv·(Σ + y2[d]) + b2 ) -------
// 16 threads per node; lanes 0..11 own one float4 chunk (48 padded cols),
// lanes 12..15 idle through the loop and pad the 16-lane reductions.
__global__ void k_gather2(const float* __restrict__ b2, float* __restrict__ out) {
    int t = threadIdx.x;
    int node = blockIdx.x * 16 + (t >> 4);
    int c = t & 15;
    bool act = (c < 12);
    float di = g_dinv[node];
    float4 v = make_float4(-1e30f, -1e30f, -1e30f, -1e30f);

    if (act) {
        const float4* y = (const float4*)g_y2;
        float4 a0 = __ldg(&y[(size_t)node * 12 + c]);   // self term (unscaled)
        float4 a1 = make_float4(0.f, 0.f, 0.f, 0.f);
        float4 a2 = make_float4(0.f, 0.f, 0.f, 0.f);
        float4 a3 = make_float4(0.f, 0.f, 0.f, 0.f);
        int j   = g_start[node];
        int end = j + g_cnt[node];
        for (; j + 4 <= end; j += 4) {                   // MLP=4
            int s0 = g_col[j + 0], s1 = g_col[j + 1];
            int s2 = g_col[j + 2], s3 = g_col[j + 3];
            float4 v0 = __ldg(&y[(size_t)s0 * 12 + c]);
            float4 v1 = __ldg(&y[(size_t)s1 * 12 + c]);
            float4 v2 = __ldg(&y[(size_t)s2 * 12 + c]);
            float4 v3 = __ldg(&y[(size_t)s3 * 12 + c]);
            a0.x += v0.x; a0.y += v0.y; a0.z += v0.z; a0.w += v0.w;
            a1.x += v1.x; a1.y += v1.y; a1.z += v1.z; a1.w += v1.w;
            a2.x += v2.x; a2.y += v2.y; a2.z += v2.z; a2.w += v2.w;
            a3.x += v3.x; a3.y += v3.y; a3.z += v3.z; a3.w += v3.w;
        }
        for (; j < end; ++j) {
            int s = g_col[j];
            float4 w = __ldg(&y[(size_t)s * 12 + c]);
            a0.x += w.x; a0.y += w.y; a0.z += w.z; a0.w += w.w;
        }
        a0.x += a1.x + a2.x + a3.x;
        a0.y += a1.y + a2.y + a3.y;
        a0.z += a1.z + a2.z + a3.z;
        a0.w += a1.w + a2.w + a3.w;

        // bias (b2 has exactly 47 floats: scalar loads for the last chunk)
        float bx, by, bz, bw;
        if (c < 11) {
            bx = b2[c * 4 + 0]; by = b2[c * 4 + 1];
            bz = b2[c * 4 + 2]; bw = b2[c * 4 + 3];
        } else {
            bx = b2[44]; by = b2[45]; bz = b2[46]; bw = 0.f;
        }
        v.x = fmaf(a0.x, di, bx);
        v.y = fmaf(a0.y, di, by);
        v.z = fmaf(a0.z, di, bz);
        v.w = (c < 11) ? fmaf(a0.w, di, bw) : -1e30f;   // col 47 is padding
    }

    // 16-lane group reductions (width=16 segments of the warp)
    float m = fmaxf(fmaxf(v.x, v.y), fmaxf(v.z, v.w));
#pragma unroll
    for (int off = 1; off < 16; off <<= 1)
        m = fmaxf(m, __shfl_xor_sync(0xffffffffu, m, off, 16));

    float s = act ? (expf(v.x - m) + expf(v.y - m) + expf(v.z - m) + expf(v.w - m))
                  : 0.f;
#pragma unroll
    for (int off = 1; off < 16; off <<= 1)
        s += __shfl_xor_sync(0xffffffffu, s, off, 16);

    float ls = m + logf(s);
    if (act) {
        size_t base = (size_t)node * F_OUT + c * 4;
        out[base + 0] = v.x - ls;
        out[base + 1] = v.y - ls;
        out[base + 2] = v.z - ls;
        if (c < 11) out[base + 3] = v.w - ls;
    }
}

// ---------------- launch (6 kernels + 2 memset nodes, graph-capturable) ----------------
extern "C" void kernel_launch(void* const* d_in, const int* in_sizes, int n_in,
                              void* d_out, int out_size) {
    const float* x  = (const float*)d_in[0];
    const int*   ei = (const int*)  d_in[1];
    const float* W1 = (const float*)d_in[2];
    const float* b1 = (const float*)d_in[3];
    const float* W2 = (const float*)d_in[4];
    const float* b2 = (const float*)d_in[5];
    float* out = (float*)d_out;
    const int* src = ei;
    const int* dst = ei + N_EDGES;

    // zero counters via memset nodes (capturable, no kernel launch)
    void *p_cnt = nullptr, *p_alloc = nullptr;
    cudaGetSymbolAddress(&p_cnt,   g_cnt);
    cudaGetSymbolAddress(&p_alloc, g_alloc);
    cudaMemsetAsync(p_cnt,   0, N_NODES * sizeof(int));
    cudaMemsetAsync(p_alloc, 0, sizeof(int));

    // CSR build
    k_cnt     <<<(N_EDGES + 255) / 256, 256>>>(dst);
    k_scanfix <<<NBLK_N, 256>>>();
    k_fill    <<<(N_EDGES + 255) / 256, 256>>>(src, dst);

    // layer 1 GEMM, then fused gather1+GEMM2, then fused gather2+softmax
    k_gemm1   <<<N_NODES / 16, 256>>>(x, W1);
    k_g1g2    <<<N_NODES / 16, 256>>>(b1, W2);
    k_gather2 <<<N_NODES / 16, 256>>>(b2, out);
}